// round 10
// baseline (speedup 1.0000x reference)
#include <cuda_runtime.h>
#include <math.h>

// Problem constants (fixed by the reference)
#define NE 16
#define NW 3
#define NB 64
#define NP 4096
#define BP (NB * NP)        // 262144 floats per (expert,proj) plane
#define PL4 (BP / 4)        // 65536 float4 per plane
#define P4 (NP / 4)         // 1024
#define TILE4 64            // float4 slots per block tile
#define NTILE (PL4 / TILE4) // 1024 blocks
#define NM 48               // mean planes: 16 Qm + 16 Km + 16 Vm
#define SM_F4 (NM * TILE4)  // 3072 float4 = 49152 B
#define THREADS 256

__global__ void __launch_bounds__(THREADS, 4)
cantor_attn_kernel(const float4* __restrict__ Qp,
                   const float4* __restrict__ Kp,
                   const float4* __restrict__ Vp,
                   const float*  __restrict__ betas,
                   const float*  __restrict__ temperature,
                   const int*    __restrict__ routes,
                   float4*       __restrict__ out)
{
    extern __shared__ float4 sm[];     // [NM][TILE4] mean planes
    __shared__ int   s_route[NE * NW];
    __shared__ float s_gate[NE * NW];  // sigmoid(beta) * inv  (pre-folded)

    const int t  = threadIdx.x;
    const int tb = blockIdx.x * TILE4; // base float4 index of this tile

    if (t < NE * NW) {
        const int e = t / NW;
        const int r = routes[t];
        s_route[t] = r;
        const float inv  = __fdividef(1.0f, sqrtf(128.0f) * fabsf(temperature[0]));
        const float gate = (r != e) ? __fdividef(1.0f, 1.0f + __expf(-betas[t])) : 1.0f;
        s_gate[t] = gate * inv;
    }

    // ---- Phase 1: stream raw planes, write 48 mean planes to smem ----
    // work item w in [0, NM*TILE4): mean-plane m = w>>6, slot s = w&63.
    // m in [0,16) -> Qm[e=m]; [16,32) -> Km[e=m-16]; [32,48) -> Vm[e=m-32].
    #pragma unroll
    for (int j = 0; j < SM_F4 / THREADS; j++) {      // 12 iterations
        const int w = t + j * THREADS;
        const int m = w >> 6;
        const int s = w & (TILE4 - 1);
        const int e = m & 15;
        const float4* __restrict__ base = (m < 16) ? Qp : ((m < 32) ? Kp : Vp);
        const float4 a = base[(long)(2 * e)     * PL4 + tb + s];
        const float4 b = base[(long)(2 * e + 1) * PL4 + tb + s];
        float4 mn;
        mn.x = 0.5f * (a.x + b.x);
        mn.y = 0.5f * (a.y + b.y);
        mn.z = 0.5f * (a.z + b.z);
        mn.w = 0.5f * (a.w + b.w);
        sm[w] = mn;
    }
    __syncthreads();

    // ---- Phase 2: 16 experts from smem means ----
    const int s   = t & (TILE4 - 1);     // slot
    const int grp = t >> 6;              // expert quarter (0..3)
    const int f4  = tb + s;
    const int b   = f4 >> 10;            // / P4
    const int p4i = f4 & (P4 - 1);
    float4* __restrict__ outp = out + (long)b * (NE * P4) + p4i;

    #pragma unroll
    for (int k = 0; k < 4; k++) {
        const int e  = grp * 4 + k;
        const int r0 = s_route[e * NW + 0];
        const int r1 = s_route[e * NW + 1];
        const int r2 = s_route[e * NW + 2];
        const float g0 = s_gate[e * NW + 0];   // sigmoid*inv
        const float g1 = s_gate[e * NW + 1];
        const float g2 = s_gate[e * NW + 2];

        const float4 qm = sm[e * TILE4 + s];
        const float4 k0 = sm[(16 + r0) * TILE4 + s];
        const float4 k1 = sm[(16 + r1) * TILE4 + s];
        const float4 k2 = sm[(16 + r2) * TILE4 + s];
        const float4 v0 = sm[(32 + r0) * TILE4 + s];
        const float4 v1 = sm[(32 + r1) * TILE4 + s];
        const float4 v2 = sm[(32 + r2) * TILE4 + s];

        float4 res;

#define DO_LANE(c)                                                         \
        {                                                                  \
            const float s0 = qm.c * g0 * k0.c;                             \
            const float s1 = qm.c * g1 * k1.c;                             \
            const float s2 = qm.c * g2 * k2.c;                             \
            const float x0 = __expf(s0);                                   \
            const float x1 = __expf(s1);                                   \
            const float x2 = __expf(s2);                                   \
            const float rs = __fdividef(1.0f, x0 + x1 + x2);               \
            res.c = (x0 * v0.c + x1 * v1.c + x2 * v2.c) * rs;              \
        }
        DO_LANE(x)
        DO_LANE(y)
        DO_LANE(z)
        DO_LANE(w)
#undef DO_LANE

        outp[(long)e * P4] = res;
    }
}

extern "C" void kernel_launch(void* const* d_in, const int* in_sizes, int n_in,
                              void* d_out, int out_size)
{
    // metadata order: Q_proj, K_proj, V_proj, betas, temperature, routes, num_patches
    const float4* Qp    = (const float4*)d_in[0];
    const float4* Kp    = (const float4*)d_in[1];
    const float4* Vp    = (const float4*)d_in[2];
    const float*  betas = (const float*)d_in[3];
    const float*  temp  = (const float*)d_in[4];
    const int*    routes= (const int*)d_in[5];
    float4*       out   = (float4*)d_out;

    (void)in_sizes; (void)n_in; (void)out_size;

    const int smem_bytes = SM_F4 * sizeof(float4);   // 49152
    static bool attr_set = false;
    if (!attr_set) {
        cudaFuncSetAttribute(cantor_attn_kernel,
                             cudaFuncAttributeMaxDynamicSharedMemorySize, smem_bytes);
        attr_set = true;
    }

    cantor_attn_kernel<<<NTILE, THREADS, smem_bytes>>>(
        Qp, Kp, Vp, betas, temp, routes, out);
}

// round 11
// speedup vs baseline: 1.1664x; 1.1664x over previous
#include <cuda_runtime.h>
#include <math.h>
#include <cstdint>

// Problem constants (fixed by the reference)
#define NE 16
#define NW 3
#define NB 64
#define NP 4096
#define BP (NB * NP)        // 262144 floats per (expert,proj) plane
#define PL4 (BP / 4)        // 65536 float4 per plane
#define P4 (NP / 4)         // 1024
#define TILE4 32            // float4 slots per block tile
#define NTILE (PL4 / TILE4) // 2048 blocks
#define NRAW 96             // raw planes staged: 32 Q + 32 K + 32 V
#define SM_F4 (NRAW * TILE4) // 3072 float4 = 49152 B
#define THREADS 256

__global__ void __launch_bounds__(THREADS, 3)
cantor_attn_kernel(const float4* __restrict__ Qp,
                   const float4* __restrict__ Kp,
                   const float4* __restrict__ Vp,
                   const float*  __restrict__ betas,
                   const float*  __restrict__ temperature,
                   const int*    __restrict__ routes,
                   float4*       __restrict__ out)
{
    extern __shared__ float4 smr[];    // [NRAW][TILE4] raw planes
    __shared__ int   s_route[NE * NW];
    __shared__ float s_gate[NE * NW];  // sigmoid(beta) * inv * 0.25 (pre-folded)

    const int t  = threadIdx.x;
    const int tb = blockIdx.x * TILE4;      // base float4 index of this tile
    const uint32_t smb = (uint32_t)__cvta_generic_to_shared(smr);

    // ---- Phase 1: stage 96 raw plane strips via cp.async (bypasses L1/MSHR) ----
    // item w in [0, NRAW*TILE4): plane = w>>5, slot = w&31.
    // planes [0,32) = Q[2e+pr], [32,64) = K, [64,96) = V.
    #pragma unroll
    for (int j = 0; j < SM_F4 / THREADS; j++) {        // 12 iterations
        const int w  = t + j * THREADS;
        const int pl = w >> 5;
        const int s  = w & (TILE4 - 1);
        const float4* src;
        if (pl < 32)      src = Qp + (long)pl        * PL4 + tb + s;
        else if (pl < 64) src = Kp + (long)(pl - 32) * PL4 + tb + s;
        else              src = Vp + (long)(pl - 64) * PL4 + tb + s;
        const uint32_t dst = smb + (uint32_t)w * 16u;
        asm volatile("cp.async.cg.shared.global [%0], [%1], 16;"
                     :: "r"(dst), "l"(src) : "memory");
    }
    asm volatile("cp.async.commit_group;" ::: "memory");

    // param staging overlaps the async copies
    if (t < NE * NW) {
        const int e = t / NW;
        const int r = routes[t];
        s_route[t] = r;
        const float inv  = __fdividef(1.0f, sqrtf(128.0f) * fabsf(temperature[0]));
        const float gate = (r != e) ? __fdividef(1.0f, 1.0f + __expf(-betas[t])) : 1.0f;
        s_gate[t] = gate * inv * 0.25f;   // folds the two 0.5 mean factors
    }

    asm volatile("cp.async.wait_group 0;" ::: "memory");
    __syncthreads();

    // ---- Phase 2: 16 experts from raw smem (means folded on the fly) ----
    const int s   = t & (TILE4 - 1);     // slot
    const int grp = t >> 5;              // 8 groups, 2 experts each
    const int f4  = tb + s;
    const int b   = f4 >> 10;            // / P4
    const int p4i = f4 & (P4 - 1);
    float4* __restrict__ outp = out + (long)b * (NE * P4) + p4i;

    #pragma unroll
    for (int k = 0; k < 2; k++) {
        const int e  = grp * 2 + k;
        const int r0 = s_route[e * NW + 0];
        const int r1 = s_route[e * NW + 1];
        const int r2 = s_route[e * NW + 2];
        const float g0 = s_gate[e * NW + 0];   // sigmoid*inv*0.25
        const float g1 = s_gate[e * NW + 1];
        const float g2 = s_gate[e * NW + 2];

        const float4 qa  = smr[(2 * e)     * TILE4 + s];
        const float4 qb  = smr[(2 * e + 1) * TILE4 + s];
        const float4 kA0 = smr[(32 + 2 * r0)     * TILE4 + s];
        const float4 kB0 = smr[(32 + 2 * r0 + 1) * TILE4 + s];
        const float4 kA1 = smr[(32 + 2 * r1)     * TILE4 + s];
        const float4 kB1 = smr[(32 + 2 * r1 + 1) * TILE4 + s];
        const float4 kA2 = smr[(32 + 2 * r2)     * TILE4 + s];
        const float4 kB2 = smr[(32 + 2 * r2 + 1) * TILE4 + s];
        const float4 vA0 = smr[(64 + 2 * r0)     * TILE4 + s];
        const float4 vB0 = smr[(64 + 2 * r0 + 1) * TILE4 + s];
        const float4 vA1 = smr[(64 + 2 * r1)     * TILE4 + s];
        const float4 vB1 = smr[(64 + 2 * r1 + 1) * TILE4 + s];
        const float4 vA2 = smr[(64 + 2 * r2)     * TILE4 + s];
        const float4 vB2 = smr[(64 + 2 * r2 + 1) * TILE4 + s];

        float4 res;

#define DO_LANE(c)                                                          \
        {                                                                   \
            const float qt = qa.c + qb.c;                                   \
            const float s0 = qt * g0 * (kA0.c + kB0.c);                     \
            const float s1 = qt * g1 * (kA1.c + kB1.c);                     \
            const float s2 = qt * g2 * (kA2.c + kB2.c);                     \
            const float x0 = __expf(s0);                                    \
            const float x1 = __expf(s1);                                    \
            const float x2 = __expf(s2);                                    \
            const float rs = __fdividef(0.5f, x0 + x1 + x2);                \
            const float nu = x0 * (vA0.c + vB0.c)                           \
                           + x1 * (vA1.c + vB1.c)                           \
                           + x2 * (vA2.c + vB2.c);                          \
            res.c = nu * rs;                                                \
        }
        DO_LANE(x)
        DO_LANE(y)
        DO_LANE(z)
        DO_LANE(w)
#undef DO_LANE

        outp[(long)e * P4] = res;
    }
}

extern "C" void kernel_launch(void* const* d_in, const int* in_sizes, int n_in,
                              void* d_out, int out_size)
{
    // metadata order: Q_proj, K_proj, V_proj, betas, temperature, routes, num_patches
    const float4* Qp    = (const float4*)d_in[0];
    const float4* Kp    = (const float4*)d_in[1];
    const float4* Vp    = (const float4*)d_in[2];
    const float*  betas = (const float*)d_in[3];
    const float*  temp  = (const float*)d_in[4];
    const int*    routes= (const int*)d_in[5];
    float4*       out   = (float4*)d_out;

    (void)in_sizes; (void)n_in; (void)out_size;

    const int smem_bytes = SM_F4 * sizeof(float4);   // 49152
    static bool attr_set = false;
    if (!attr_set) {
        cudaFuncSetAttribute(cantor_attn_kernel,
                             cudaFuncAttributeMaxDynamicSharedMemorySize, smem_bytes);
        attr_set = true;
    }

    cantor_attn_kernel<<<NTILE, THREADS, smem_bytes>>>(
        Qp, Kp, Vp, betas, temp, routes, out);
}